// round 1
// baseline (speedup 1.0000x reference)
#include <cuda_runtime.h>
#include <math.h>

// ---------------- problem constants ----------------
#define Bb    2
#define GHc   64
#define GWc   64
#define Dm    384
#define Hh    12
#define HDc   32
#define QG    22            // (64+6-7)/3+1
#define NQ    484           // 22*22
#define NK    4096          // 64*64
#define BH    24            // B*H
#define ITERS 3
#define KCOL  18816         // 384*7*7
#define MROWS 968           // B*NQ
#define NTOK  8192          // B*NK
#define LN_EPSF 1e-5f
#define EPSF  1.1920929e-07f

// ---------------- scratch (static device memory; no allocs) ----------------
__device__ float g_col[MROWS * KCOL];          // 72.9 MB im2col
__device__ float g_convC[MROWS * Dm];
__device__ float g_xout[MROWS * Dm];
__device__ float g_kv[NTOK * 2 * Dm];
__device__ float g_k[BH * NK * HDc];
__device__ float g_vT[BH * HDc * NK];
__device__ float g_vs[BH * HDc * NK];
__device__ float g_q[BH * NQ * HDc];
__device__ float g_qlin[MROWS * Dm];
__device__ float g_attn[(long long)BH * NQ * NK];   // 190 MB
__device__ float g_csum[BH * NK];
__device__ float g_upd[BH * NQ * HDc];
__device__ float g_h1[MROWS * 4 * Dm];
__device__ float g_h2[MROWS * Dm];
__device__ float g_kvwT[2 * Dm * Dm];
__device__ float g_qwT[Dm * Dm];
__device__ float g_w1T[4 * Dm * Dm];
__device__ float g_w2T[Dm * 4 * Dm];

// ---------------- generic NT GEMM: C[M,N] = A[M,K] * B[N,K]^T (+bias) ------
// batched via blockIdx.z with element strides sA,sB,sC.
__global__ void gemm_nt(const float* __restrict__ A, const float* __restrict__ Bp,
                        float* __restrict__ C, const float* __restrict__ bias,
                        int M, int N, int K,
                        long long sA, long long sB, long long sC)
{
    A  += (long long)blockIdx.z * sA;
    Bp += (long long)blockIdx.z * sB;
    C  += (long long)blockIdx.z * sC;

    __shared__ __align__(16) float As[16][68];
    __shared__ __align__(16) float Bs[16][68];

    const int t  = threadIdx.x;            // 256 threads
    const int tx = t & 15, ty = t >> 4;
    const int m0 = blockIdx.y * 64, n0 = blockIdx.x * 64;
    const int lrow = t >> 2;
    const int lvec = (t & 3) * 4;

    float acc[4][4] = {};
    for (int k0 = 0; k0 < K; k0 += 16) {
        float4 av = make_float4(0.f,0.f,0.f,0.f);
        float4 bv = make_float4(0.f,0.f,0.f,0.f);
        int am = m0 + lrow;
        if (am < M) av = *(const float4*)(A + (long long)am * K + k0 + lvec);
        int bn = n0 + lrow;
        if (bn < N) bv = *(const float4*)(Bp + (long long)bn * K + k0 + lvec);
        As[lvec+0][lrow] = av.x; As[lvec+1][lrow] = av.y;
        As[lvec+2][lrow] = av.z; As[lvec+3][lrow] = av.w;
        Bs[lvec+0][lrow] = bv.x; Bs[lvec+1][lrow] = bv.y;
        Bs[lvec+2][lrow] = bv.z; Bs[lvec+3][lrow] = bv.w;
        __syncthreads();
        #pragma unroll
        for (int k = 0; k < 16; k++) {
            float4 a = *(const float4*)&As[k][ty*4];
            float4 b = *(const float4*)&Bs[k][tx*4];
            acc[0][0] += a.x*b.x; acc[0][1] += a.x*b.y; acc[0][2] += a.x*b.z; acc[0][3] += a.x*b.w;
            acc[1][0] += a.y*b.x; acc[1][1] += a.y*b.y; acc[1][2] += a.y*b.z; acc[1][3] += a.y*b.w;
            acc[2][0] += a.z*b.x; acc[2][1] += a.z*b.y; acc[2][2] += a.z*b.z; acc[2][3] += a.z*b.w;
            acc[3][0] += a.w*b.x; acc[3][1] += a.w*b.y; acc[3][2] += a.w*b.z; acc[3][3] += a.w*b.w;
        }
        __syncthreads();
    }
    #pragma unroll
    for (int i = 0; i < 4; i++) {
        int m = m0 + ty*4 + i;
        if (m >= M) continue;
        #pragma unroll
        for (int j = 0; j < 4; j++) {
            int n = n0 + tx*4 + j;
            if (n >= N) continue;
            float v = acc[i][j];
            if (bias) v += bias[n];
            C[(long long)m * N + n] = v;
        }
    }
}

// split-K NT GEMM (z = K chunk), accumulates with atomicAdd into pre-filled C
__global__ void gemm_nt_splitk(const float* __restrict__ A, const float* __restrict__ Bp,
                               float* __restrict__ C, int M, int N, int Ktot)
{
    const int Kc = Ktot / gridDim.z;
    const float* Ap = A  + (long long)blockIdx.z * Kc;
    const float* Bq = Bp + (long long)blockIdx.z * Kc;

    __shared__ __align__(16) float As[16][68];
    __shared__ __align__(16) float Bs[16][68];

    const int t  = threadIdx.x;
    const int tx = t & 15, ty = t >> 4;
    const int m0 = blockIdx.y * 64, n0 = blockIdx.x * 64;
    const int lrow = t >> 2;
    const int lvec = (t & 3) * 4;

    float acc[4][4] = {};
    for (int k0 = 0; k0 < Kc; k0 += 16) {
        float4 av = make_float4(0.f,0.f,0.f,0.f);
        float4 bv = make_float4(0.f,0.f,0.f,0.f);
        int am = m0 + lrow;
        if (am < M) av = *(const float4*)(Ap + (long long)am * Ktot + k0 + lvec);
        int bn = n0 + lrow;
        if (bn < N) bv = *(const float4*)(Bq + (long long)bn * Ktot + k0 + lvec);
        As[lvec+0][lrow] = av.x; As[lvec+1][lrow] = av.y;
        As[lvec+2][lrow] = av.z; As[lvec+3][lrow] = av.w;
        Bs[lvec+0][lrow] = bv.x; Bs[lvec+1][lrow] = bv.y;
        Bs[lvec+2][lrow] = bv.z; Bs[lvec+3][lrow] = bv.w;
        __syncthreads();
        #pragma unroll
        for (int k = 0; k < 16; k++) {
            float4 a = *(const float4*)&As[k][ty*4];
            float4 b = *(const float4*)&Bs[k][tx*4];
            acc[0][0] += a.x*b.x; acc[0][1] += a.x*b.y; acc[0][2] += a.x*b.z; acc[0][3] += a.x*b.w;
            acc[1][0] += a.y*b.x; acc[1][1] += a.y*b.y; acc[1][2] += a.y*b.z; acc[1][3] += a.y*b.w;
            acc[2][0] += a.z*b.x; acc[2][1] += a.z*b.y; acc[2][2] += a.z*b.z; acc[2][3] += a.z*b.w;
            acc[3][0] += a.w*b.x; acc[3][1] += a.w*b.y; acc[3][2] += a.w*b.z; acc[3][3] += a.w*b.w;
        }
        __syncthreads();
    }
    #pragma unroll
    for (int i = 0; i < 4; i++) {
        int m = m0 + ty*4 + i;
        if (m >= M) continue;
        #pragma unroll
        for (int j = 0; j < 4; j++) {
            int n = n0 + tx*4 + j;
            if (n >= N) continue;
            atomicAdd(&C[(long long)m * N + n], acc[i][j]);
        }
    }
}

// ---------------- helper kernels ----------------
__global__ void transpose_kn(const float* __restrict__ W, float* __restrict__ WT, int K, int N)
{
    long long idx = (long long)blockIdx.x * blockDim.x + threadIdx.x;
    if (idx >= (long long)K * N) return;
    int n = (int)(idx % N), k = (int)(idx / N);
    WT[(long long)n * K + k] = W[idx];
}

__global__ void im2col_kernel(const float* __restrict__ x, float* __restrict__ col)
{
    long long idx = (long long)blockIdx.x * blockDim.x + threadIdx.x;
    if (idx >= (long long)MROWS * KCOL) return;
    int m = (int)(idx / KCOL), kidx = (int)(idx % KCOL);
    int b = m / NQ, nq = m % NQ;
    int oh = nq / QG, ow = nq % QG;
    int ci = kidx / 49, r = kidx % 49;
    int kh = r / 7, kw = r % 7;
    int ih = oh * 3 - 3 + kh, iw = ow * 3 - 3 + kw;
    float v = 0.f;
    if (ih >= 0 && ih < GHc && iw >= 0 && iw < GWc)
        v = x[((long long)b * NK + ih * GWc + iw) * Dm + ci];
    col[idx] = v;
}

__global__ void fill_bias_kernel(float* __restrict__ C, const float* __restrict__ b, long long total, int N)
{
    long long idx = (long long)blockIdx.x * blockDim.x + threadIdx.x;
    if (idx >= total) return;
    C[idx] = b[idx % N];
}

// LayerNorm over D=384. gather_heads: src is (bh, i, d) layout. add_to: dst += ln
__global__ void ln_kernel(const float* __restrict__ src, const float* __restrict__ gam,
                          const float* __restrict__ bet, float* __restrict__ dst,
                          int gather_heads, int add_to)
{
    int row = blockIdx.x;     // 0..967
    int t = threadIdx.x;      // 128
    __shared__ float red[128];
    int b = row / NQ, i = row % NQ;
    float v[3];
    #pragma unroll
    for (int u = 0; u < 3; u++) {
        int c = t + u * 128;
        if (gather_heads) {
            int h = c >> 5, d = c & 31;
            v[u] = src[(((long long)(b * Hh + h)) * NQ + i) * HDc + d];
        } else {
            v[u] = src[(long long)row * Dm + c];
        }
    }
    float s = v[0] + v[1] + v[2];
    red[t] = s; __syncthreads();
    for (int o = 64; o > 0; o >>= 1) { if (t < o) red[t] += red[t + o]; __syncthreads(); }
    float mu = red[0] * (1.f / 384.f);
    __syncthreads();
    float sq = 0.f;
    #pragma unroll
    for (int u = 0; u < 3; u++) { float d = v[u] - mu; sq += d * d; }
    red[t] = sq; __syncthreads();
    for (int o = 64; o > 0; o >>= 1) { if (t < o) red[t] += red[t + o]; __syncthreads(); }
    float rstd = rsqrtf(red[0] * (1.f / 384.f) + LN_EPSF);
    #pragma unroll
    for (int u = 0; u < 3; u++) {
        int c = t + u * 128;
        float y = (v[u] - mu) * rstd * gam[c] + bet[c];
        long long o = (long long)row * Dm + c;
        if (add_to) dst[o] += y; else dst[o] = y;
    }
}

// Rotary spatial embedding: src rows (b*N+n) with stride srow, head slice at soff+h*32.
// dst layout: ((b*H+h)*N + n)*32 + d. Optional global scale (temp).
__global__ void rose_kernel(const float* __restrict__ src, int srow, int soff,
                            const float* __restrict__ freqs, const float* __restrict__ tempp,
                            float* __restrict__ dst, int Ntok, int gw, float sp)
{
    int idx = blockIdx.x * blockDim.x + threadIdx.x;
    if (idx >= Bb * Hh * Ntok) return;
    int n = idx % Ntok, bh = idx / Ntok;
    int h = bh % Hh, b = bh / Hh;
    const float* row = src + ((long long)(b * Ntok + n)) * srow + soff + h * HDc;
    float c0 = (float)(n / gw) * sp;
    float c1 = (float)(n % gw) * sp;
    float sc = tempp ? tempp[0] : 1.f;
    float* o = dst + (long long)idx * HDc;
    #pragma unroll
    for (int tt = 0; tt < 8; tt++) {
        float f = freqs[h * 8 + tt];
        float ang = ((tt < 4) ? c0 : c1) * f;
        float sn, cs;
        sincosf(ang, &sn, &cs);
        float x1 = row[2 * tt], x2 = row[2 * tt + 1];
        o[2 * tt]     = sc * (x1 * cs - x2 * sn);
        o[2 * tt + 1] = sc * (x1 * sn + x2 * cs);
    }
    #pragma unroll
    for (int d = 16; d < 32; d++) o[d] = sc * row[d];
}

// vT[(bh*32+d)*NK + j] = kv[(b*NK+j)*768 + 384 + h*32 + d]
__global__ void build_vT_kernel(const float* __restrict__ kv, float* __restrict__ vT)
{
    long long idx = (long long)blockIdx.x * blockDim.x + threadIdx.x;
    if (idx >= (long long)BH * HDc * NK) return;
    int j = (int)(idx % NK);
    int r = (int)(idx / NK);
    int d = r % HDc, bh = r / HDc;
    int h = bh % Hh, b = bh / Hh;
    vT[idx] = kv[((long long)(b * NK + j)) * (2 * Dm) + Dm + h * HDc + d];
}

__global__ void vscale_kernel(const float* __restrict__ vT, const float* __restrict__ csum,
                              float* __restrict__ vs)
{
    long long idx = (long long)blockIdx.x * blockDim.x + threadIdx.x;
    if (idx >= (long long)BH * HDc * NK) return;
    int j = (int)(idx % NK);
    int bh = (int)(idx / ((long long)HDc * NK));
    vs[idx] = vT[idx] / (csum[bh * NK + j] + EPSF);
}

__global__ void softmax_kernel(float* __restrict__ S)
{
    long long row = blockIdx.x;
    float* p = S + row * NK;
    int t = threadIdx.x;   // 256
    float vals[16];
    float mx = -INFINITY;
    #pragma unroll
    for (int u = 0; u < 16; u++) { vals[u] = p[t + u * 256]; mx = fmaxf(mx, vals[u]); }
    __shared__ float red[256];
    red[t] = mx; __syncthreads();
    for (int o = 128; o > 0; o >>= 1) { if (t < o) red[t] = fmaxf(red[t], red[t + o]); __syncthreads(); }
    mx = red[0]; __syncthreads();
    float s = 0.f;
    #pragma unroll
    for (int u = 0; u < 16; u++) { vals[u] = expf(vals[u] - mx); s += vals[u]; }
    red[t] = s; __syncthreads();
    for (int o = 128; o > 0; o >>= 1) { if (t < o) red[t] += red[t + o]; __syncthreads(); }
    float inv = 1.f / red[0];
    #pragma unroll
    for (int u = 0; u < 16; u++) p[t + u * 256] = vals[u] * inv;
}

__global__ void colsum_kernel(const float* __restrict__ S, float* __restrict__ csum)
{
    int j = blockIdx.x * 256 + threadIdx.x;
    int bh = blockIdx.y;
    const float* p = S + (long long)bh * NQ * NK + j;
    float s = 0.f;
    for (int i = 0; i < NQ; i++) s += p[(long long)i * NK];
    csum[bh * NK + j] = s;
}

__global__ void gelu_kernel(float* __restrict__ h, long long n)
{
    long long idx = (long long)blockIdx.x * blockDim.x + threadIdx.x;
    if (idx >= n) return;
    float v = h[idx];
    h[idx] = 0.5f * v * (1.f + erff(v * 0.70710678118654752f));
}

__global__ void out_x_kernel(float* __restrict__ out, const float* __restrict__ x)
{
    int idx = blockIdx.x * blockDim.x + threadIdx.x;
    if (idx >= MROWS * Dm) return;
    out[idx] = x[idx];
}

__global__ void out_attn_kernel(float* __restrict__ outq, float* __restrict__ outk,
                                const float* __restrict__ S, const float* __restrict__ csum)
{
    long long idx = (long long)blockIdx.x * blockDim.x + threadIdx.x;
    if (idx >= (long long)BH * NQ * NK) return;
    int j = (int)(idx % NK);
    int bh = (int)(idx / ((long long)NQ * NK));
    float a = S[idx];
    outk[idx] = a;
    outq[idx] = a / (csum[bh * NK + j] + EPSF);
}

// ---------------- host ----------------
static float* sym_addr(const void* p) { return (float*)p; }

extern "C" void kernel_launch(void* const* d_in, const int* in_sizes, int n_in,
                              void* d_out, int out_size)
{
    const float* x      = (const float*)d_in[0];
    const float* conv_w = (const float*)d_in[1];
    const float* conv_b = (const float*)d_in[2];
    const float* kv_w   = (const float*)d_in[3];
    const float* kv_b   = (const float*)d_in[4];
    const float* q_w    = (const float*)d_in[5];
    const float* q_b    = (const float*)d_in[6];
    const float* w1     = (const float*)d_in[7];
    const float* b1m    = (const float*)d_in[8];
    const float* w2     = (const float*)d_in[9];
    const float* b2m    = (const float*)d_in[10];
    const float* g1     = (const float*)d_in[11];
    const float* b1g    = (const float*)d_in[12];
    const float* g2     = (const float*)d_in[13];
    const float* b2g    = (const float*)d_in[14];
    const float* g3     = (const float*)d_in[15];
    const float* b3g    = (const float*)d_in[16];
    const float* temp   = (const float*)d_in[17];
    const float* freqs  = (const float*)d_in[18];
    float* out = (float*)d_out;

    static float *p_col=0,*p_convC=0,*p_xout=0,*p_kv=0,*p_k=0,*p_vT=0,*p_vs=0,*p_q=0,
                 *p_qlin=0,*p_attn=0,*p_csum=0,*p_upd=0,*p_h1=0,*p_h2=0,
                 *p_kvwT=0,*p_qwT=0,*p_w1T=0,*p_w2T=0;
    if (!p_col) {
        void* t;
        cudaGetSymbolAddress(&t, g_col);   p_col   = (float*)t;
        cudaGetSymbolAddress(&t, g_convC); p_convC = (float*)t;
        cudaGetSymbolAddress(&t, g_xout);  p_xout  = (float*)t;
        cudaGetSymbolAddress(&t, g_kv);    p_kv    = (float*)t;
        cudaGetSymbolAddress(&t, g_k);     p_k     = (float*)t;
        cudaGetSymbolAddress(&t, g_vT);    p_vT    = (float*)t;
        cudaGetSymbolAddress(&t, g_vs);    p_vs    = (float*)t;
        cudaGetSymbolAddress(&t, g_q);     p_q     = (float*)t;
        cudaGetSymbolAddress(&t, g_qlin);  p_qlin  = (float*)t;
        cudaGetSymbolAddress(&t, g_attn);  p_attn  = (float*)t;
        cudaGetSymbolAddress(&t, g_csum);  p_csum  = (float*)t;
        cudaGetSymbolAddress(&t, g_upd);   p_upd   = (float*)t;
        cudaGetSymbolAddress(&t, g_h1);    p_h1    = (float*)t;
        cudaGetSymbolAddress(&t, g_h2);    p_h2    = (float*)t;
        cudaGetSymbolAddress(&t, g_kvwT);  p_kvwT  = (float*)t;
        cudaGetSymbolAddress(&t, g_qwT);   p_qwT   = (float*)t;
        cudaGetSymbolAddress(&t, g_w1T);   p_w1T   = (float*)t;
        cudaGetSymbolAddress(&t, g_w2T);   p_w2T   = (float*)t;
    }

    const int TB = 256;
    // weight transposes (all GEMMs become NT form)
    transpose_kn<<<(Dm*2*Dm + TB-1)/TB, TB>>>(kv_w, p_kvwT, Dm, 2*Dm);
    transpose_kn<<<(Dm*Dm   + TB-1)/TB, TB>>>(q_w,  p_qwT,  Dm, Dm);
    transpose_kn<<<(Dm*4*Dm + TB-1)/TB, TB>>>(w1,   p_w1T,  Dm, 4*Dm);
    transpose_kn<<<(4*Dm*Dm + TB-1)/TB, TB>>>(w2,   p_w2T,  4*Dm, Dm);

    // conv via im2col + split-K GEMM
    im2col_kernel<<<(int)(((long long)MROWS*KCOL + TB-1)/TB), TB>>>(x, p_col);
    fill_bias_kernel<<<(MROWS*Dm + TB-1)/TB, TB>>>(p_convC, conv_b, (long long)MROWS*Dm, Dm);
    gemm_nt_splitk<<<dim3(6, 16, 8), TB>>>(p_col, conv_w, p_convC, MROWS, Dm, KCOL);
    ln_kernel<<<MROWS, 128>>>(p_convC, g1, b1g, p_xout, 0, 0);

    // loop-invariant: kv projection, rotated k (scaled by temp), transposed v
    gemm_nt<<<dim3(12, 128, 1), TB>>>(x, p_kvwT, p_kv, kv_b, NTOK, 2*Dm, Dm, 0, 0, 0);
    rose_kernel<<<(BH*NK + 127)/128, 128>>>(p_kv, 2*Dm, 0, freqs, temp, p_k, NK, GWc, 1.0f);
    build_vT_kernel<<<(int)(((long long)BH*HDc*NK + TB-1)/TB), TB>>>(p_kv, p_vT);

    for (int it = 0; it < ITERS; ++it) {
        // q = rose(x_out @ q_w + q_b)
        gemm_nt<<<dim3(6, 16, 1), TB>>>(p_xout, p_qwT, p_qlin, q_b, MROWS, Dm, Dm, 0, 0, 0);
        rose_kernel<<<(BH*NQ + 127)/128, 128>>>(p_qlin, Dm, 0, freqs, (const float*)0, p_q, NQ, QG, 3.0f);
        // scores: batched 24 x (484 x 4096 x 32)
        gemm_nt<<<dim3(64, 8, BH), TB>>>(p_q, p_k, p_attn, (const float*)0, NQ, NK, HDc,
                                         (long long)NQ*HDc, (long long)NK*HDc, (long long)NQ*NK);
        softmax_kernel<<<BH*NQ, 256>>>(p_attn);
        colsum_kernel<<<dim3(NK/256, BH), 256>>>(p_attn, p_csum);
        // fold 1/(csum+eps) into v, then upd = attn_k @ vs^T
        vscale_kernel<<<(int)(((long long)BH*HDc*NK + TB-1)/TB), TB>>>(p_vT, p_csum, p_vs);
        gemm_nt<<<dim3(1, 8, BH), TB>>>(p_attn, p_vs, p_upd, (const float*)0, NQ, HDc, NK,
                                        (long long)NQ*NK, (long long)HDc*NK, (long long)NQ*HDc);
        // x_out += ln(upd)
        ln_kernel<<<MROWS, 128>>>(p_upd, g2, b2g, p_xout, 1, 1);
        // MLP
        gemm_nt<<<dim3(24, 16, 1), TB>>>(p_xout, p_w1T, p_h1, b1m, MROWS, 4*Dm, Dm, 0, 0, 0);
        gelu_kernel<<<(int)(((long long)MROWS*4*Dm + TB-1)/TB), TB>>>(p_h1, (long long)MROWS*4*Dm);
        gemm_nt<<<dim3(6, 16, 1), TB>>>(p_h1, p_w2T, p_h2, b2m, MROWS, Dm, 4*Dm, 0, 0, 0);
        ln_kernel<<<MROWS, 128>>>(p_h2, g3, b3g, p_xout, 0, 1);
    }

    // outputs: [x_out | attn_q | attn_k]
    out_x_kernel<<<(MROWS*Dm + TB-1)/TB, TB>>>(out, p_xout);
    float* outq = out + (long long)MROWS * Dm;
    float* outk = outq + (long long)BH * NQ * NK;
    out_attn_kernel<<<(int)(((long long)BH*NQ*NK + TB-1)/TB), TB>>>(outq, outk, p_attn, p_csum);
    (void)sym_addr; (void)in_sizes; (void)n_in; (void)out_size;
}

// round 2
// speedup vs baseline: 1.5720x; 1.5720x over previous
#include <cuda_runtime.h>
#include <math.h>

// ---------------- problem constants ----------------
#define Bb    2
#define GHc   64
#define GWc   64
#define Dm    384
#define Hh    12
#define HDc   32
#define QG    22
#define NQ    484
#define NK    4096
#define BH    24
#define ITERS 3
#define KCOL  18816
#define MROWS 968
#define NTOK  8192
#define LN_EPSF 1e-5f
#define EPSF  1.1920929e-07f

// ---------------- scratch ----------------
__device__ float g_col[MROWS * KCOL];
__device__ float g_convC[MROWS * Dm];
__device__ float g_xout[MROWS * Dm];
__device__ float g_kv[NTOK * 2 * Dm];
__device__ float g_k[BH * NK * HDc];
__device__ float g_vT[BH * HDc * NK];
__device__ float g_vs[BH * HDc * NK];
__device__ float g_q[BH * NQ * HDc];
__device__ float g_qlin[MROWS * Dm];
__device__ float g_attn[(long long)BH * NQ * NK];
__device__ float g_csum[BH * NK];
__device__ float g_upd[BH * NQ * HDc];
__device__ float g_h1[MROWS * 4 * Dm];
__device__ float g_h2[MROWS * Dm];
__device__ float g_kvwT[2 * Dm * Dm];
__device__ float g_qwT[Dm * Dm];
__device__ float g_w1T[4 * Dm * Dm];
__device__ float g_w2T[Dm * 4 * Dm];

__device__ __forceinline__ unsigned f2tf(float f) {
    unsigned u;
    asm("cvt.rna.tf32.f32 %0, %1;" : "=r"(u) : "f"(f));
    return u;
}

// ================= TF32 tensor-core NT GEMM =================
// C[M,N] = A[M,K] * B[N,K]^T (+bias). Batched via blockIdx.z; optional
// split-K (nsplit>1 -> atomicAdd into pre-initialized C, bias must be
// folded into the init).
// Block tile: 128(M) x 64(N) x 16(K). 256 threads = 8 warps (4m x 2n),
// each warp owns a 32x32 subtile = 2x4 m16n8k8 mma tiles.
__global__ void __launch_bounds__(256)
gemm_nt_tf32(const float* __restrict__ A, const float* __restrict__ Bp,
             float* __restrict__ C, const float* __restrict__ bias,
             int M, int N, int K, int nsplit,
             long long sA, long long sB, long long sC)
{
    const int bz = blockIdx.z;
    const int batch = bz / nsplit, chunk = bz - batch * nsplit;
    const int Kc = K / nsplit;
    A  += (long long)batch * sA + (long long)chunk * Kc;
    Bp += (long long)batch * sB + (long long)chunk * Kc;
    C  += (long long)batch * sC;

    __shared__ unsigned As[128][20];   // stride 20 words -> conflict-free frags
    __shared__ unsigned Bs[64][20];

    const int t = threadIdx.x;
    const int lane = t & 31, warp = t >> 5;
    const int g = lane >> 2, tig = lane & 3;
    const int wm = warp >> 1, wn = warp & 1;
    const int m0 = blockIdx.y * 128, n0 = blockIdx.x * 64;

    float acc[2][4][4];
    #pragma unroll
    for (int a = 0; a < 2; a++)
        #pragma unroll
        for (int b = 0; b < 4; b++)
            #pragma unroll
            for (int c = 0; c < 4; c++) acc[a][b][c] = 0.f;

    for (int k0 = 0; k0 < Kc; k0 += 16) {
        // stage A tile (128x16): 512 float4 loads over 256 threads
        #pragma unroll
        for (int i = 0; i < 2; i++) {
            int id = t + i * 256;
            int r = id >> 2, c4 = (id & 3) << 2;
            float4 v = make_float4(0.f, 0.f, 0.f, 0.f);
            int gm = m0 + r;
            if (gm < M) v = *(const float4*)(A + (long long)gm * K + k0 + c4);
            As[r][c4 + 0] = f2tf(v.x); As[r][c4 + 1] = f2tf(v.y);
            As[r][c4 + 2] = f2tf(v.z); As[r][c4 + 3] = f2tf(v.w);
        }
        // stage B tile (64x16): 256 float4 loads
        {
            int r = t >> 2, c4 = (t & 3) << 2;
            float4 v = make_float4(0.f, 0.f, 0.f, 0.f);
            int gn = n0 + r;
            if (gn < N) v = *(const float4*)(Bp + (long long)gn * K + k0 + c4);
            Bs[r][c4 + 0] = f2tf(v.x); Bs[r][c4 + 1] = f2tf(v.y);
            Bs[r][c4 + 2] = f2tf(v.z); Bs[r][c4 + 3] = f2tf(v.w);
        }
        __syncthreads();

        #pragma unroll
        for (int ks = 0; ks < 16; ks += 8) {
            unsigned af[2][4], bf[4][2];
            #pragma unroll
            for (int mt = 0; mt < 2; mt++) {
                int r = wm * 32 + mt * 16 + g;
                af[mt][0] = As[r][ks + tig];
                af[mt][1] = As[r + 8][ks + tig];
                af[mt][2] = As[r][ks + tig + 4];
                af[mt][3] = As[r + 8][ks + tig + 4];
            }
            #pragma unroll
            for (int nt = 0; nt < 4; nt++) {
                int r = wn * 32 + nt * 8 + g;
                bf[nt][0] = Bs[r][ks + tig];
                bf[nt][1] = Bs[r][ks + tig + 4];
            }
            #pragma unroll
            for (int mt = 0; mt < 2; mt++)
                #pragma unroll
                for (int nt = 0; nt < 4; nt++)
                    asm volatile(
                        "mma.sync.aligned.m16n8k8.row.col.f32.tf32.tf32.f32 "
                        "{%0,%1,%2,%3},{%4,%5,%6,%7},{%8,%9},{%0,%1,%2,%3};"
                        : "+f"(acc[mt][nt][0]), "+f"(acc[mt][nt][1]),
                          "+f"(acc[mt][nt][2]), "+f"(acc[mt][nt][3])
                        : "r"(af[mt][0]), "r"(af[mt][1]), "r"(af[mt][2]), "r"(af[mt][3]),
                          "r"(bf[nt][0]), "r"(bf[nt][1]));
        }
        __syncthreads();
    }

    const bool atomic = nsplit > 1;
    #pragma unroll
    for (int mt = 0; mt < 2; mt++) {
        #pragma unroll
        for (int nt = 0; nt < 4; nt++) {
            int m = m0 + wm * 32 + mt * 16 + g;
            int n = n0 + wn * 32 + nt * 8 + 2 * tig;
            if (n >= N) continue;
            float bv0 = bias ? bias[n] : 0.f;
            float bv1 = bias ? bias[n + 1] : 0.f;
            if (m < M) {
                if (atomic) {
                    atomicAdd(&C[(long long)m * N + n],     acc[mt][nt][0]);
                    atomicAdd(&C[(long long)m * N + n + 1], acc[mt][nt][1]);
                } else {
                    float2 v = make_float2(acc[mt][nt][0] + bv0, acc[mt][nt][1] + bv1);
                    *(float2*)(C + (long long)m * N + n) = v;
                }
            }
            if (m + 8 < M) {
                if (atomic) {
                    atomicAdd(&C[(long long)(m + 8) * N + n],     acc[mt][nt][2]);
                    atomicAdd(&C[(long long)(m + 8) * N + n + 1], acc[mt][nt][3]);
                } else {
                    float2 v = make_float2(acc[mt][nt][2] + bv0, acc[mt][nt][3] + bv1);
                    *(float2*)(C + (long long)(m + 8) * N + n) = v;
                }
            }
        }
    }
}

// ---------------- helper kernels ----------------
__global__ void transpose_kn(const float* __restrict__ W, float* __restrict__ WT, int K, int N)
{
    long long idx = (long long)blockIdx.x * blockDim.x + threadIdx.x;
    if (idx >= (long long)K * N) return;
    int n = (int)(idx % N), k = (int)(idx / N);
    WT[(long long)n * K + k] = W[idx];
}

__global__ void im2col_kernel(const float* __restrict__ x, float* __restrict__ col)
{
    long long idx = (long long)blockIdx.x * blockDim.x + threadIdx.x;
    if (idx >= (long long)MROWS * KCOL) return;
    int m = (int)(idx / KCOL), kidx = (int)(idx % KCOL);
    int b = m / NQ, nq = m % NQ;
    int oh = nq / QG, ow = nq % QG;
    int ci = kidx / 49, r = kidx % 49;
    int kh = r / 7, kw = r % 7;
    int ih = oh * 3 - 3 + kh, iw = ow * 3 - 3 + kw;
    float v = 0.f;
    if (ih >= 0 && ih < GHc && iw >= 0 && iw < GWc)
        v = x[((long long)b * NK + ih * GWc + iw) * Dm + ci];
    col[idx] = v;
}

__global__ void fill_bias_kernel(float* __restrict__ C, const float* __restrict__ b, long long total, int N)
{
    long long idx = (long long)blockIdx.x * blockDim.x + threadIdx.x;
    if (idx >= total) return;
    C[idx] = b[idx % N];
}

__global__ void ln_kernel(const float* __restrict__ src, const float* __restrict__ gam,
                          const float* __restrict__ bet, float* __restrict__ dst,
                          int gather_heads, int add_to)
{
    int row = blockIdx.x;
    int t = threadIdx.x;
    __shared__ float red[128];
    int b = row / NQ, i = row % NQ;
    float v[3];
    #pragma unroll
    for (int u = 0; u < 3; u++) {
        int c = t + u * 128;
        if (gather_heads) {
            int h = c >> 5, d = c & 31;
            v[u] = src[(((long long)(b * Hh + h)) * NQ + i) * HDc + d];
        } else {
            v[u] = src[(long long)row * Dm + c];
        }
    }
    float s = v[0] + v[1] + v[2];
    red[t] = s; __syncthreads();
    for (int o = 64; o > 0; o >>= 1) { if (t < o) red[t] += red[t + o]; __syncthreads(); }
    float mu = red[0] * (1.f / 384.f);
    __syncthreads();
    float sq = 0.f;
    #pragma unroll
    for (int u = 0; u < 3; u++) { float d = v[u] - mu; sq += d * d; }
    red[t] = sq; __syncthreads();
    for (int o = 64; o > 0; o >>= 1) { if (t < o) red[t] += red[t + o]; __syncthreads(); }
    float rstd = rsqrtf(red[0] * (1.f / 384.f) + LN_EPSF);
    #pragma unroll
    for (int u = 0; u < 3; u++) {
        int c = t + u * 128;
        float y = (v[u] - mu) * rstd * gam[c] + bet[c];
        long long o = (long long)row * Dm + c;
        if (add_to) dst[o] += y; else dst[o] = y;
    }
}

__global__ void rose_kernel(const float* __restrict__ src, int srow, int soff,
                            const float* __restrict__ freqs, const float* __restrict__ tempp,
                            float* __restrict__ dst, int Ntok, int gw, float sp)
{
    int idx = blockIdx.x * blockDim.x + threadIdx.x;
    if (idx >= Bb * Hh * Ntok) return;
    int n = idx % Ntok, bh = idx / Ntok;
    int h = bh % Hh, b = bh / Hh;
    const float* row = src + ((long long)(b * Ntok + n)) * srow + soff + h * HDc;
    float c0 = (float)(n / gw) * sp;
    float c1 = (float)(n % gw) * sp;
    float sc = tempp ? tempp[0] : 1.f;
    float* o = dst + (long long)idx * HDc;
    #pragma unroll
    for (int tt = 0; tt < 8; tt++) {
        float f = freqs[h * 8 + tt];
        float ang = ((tt < 4) ? c0 : c1) * f;
        float sn, cs;
        sincosf(ang, &sn, &cs);
        float x1 = row[2 * tt], x2 = row[2 * tt + 1];
        o[2 * tt]     = sc * (x1 * cs - x2 * sn);
        o[2 * tt + 1] = sc * (x1 * sn + x2 * cs);
    }
    #pragma unroll
    for (int d = 16; d < 32; d++) o[d] = sc * row[d];
}

__global__ void build_vT_kernel(const float* __restrict__ kv, float* __restrict__ vT)
{
    long long idx = (long long)blockIdx.x * blockDim.x + threadIdx.x;
    if (idx >= (long long)BH * HDc * NK) return;
    int j = (int)(idx % NK);
    int r = (int)(idx / NK);
    int d = r % HDc, bh = r / HDc;
    int h = bh % Hh, b = bh / Hh;
    vT[idx] = kv[((long long)(b * NK + j)) * (2 * Dm) + Dm + h * HDc + d];
}

__global__ void vscale_kernel(const float* __restrict__ vT, const float* __restrict__ csum,
                              float* __restrict__ vs)
{
    long long idx = (long long)blockIdx.x * blockDim.x + threadIdx.x;
    if (idx >= (long long)BH * HDc * NK) return;
    int j = (int)(idx % NK);
    int bh = (int)(idx / ((long long)HDc * NK));
    vs[idx] = vT[idx] / (csum[bh * NK + j] + EPSF);
}

__global__ void softmax_kernel(float* __restrict__ S)
{
    long long row = blockIdx.x;
    float* p = S + row * NK;
    int t = threadIdx.x;
    float vals[16];
    float mx = -INFINITY;
    #pragma unroll
    for (int u = 0; u < 16; u++) { vals[u] = p[t + u * 256]; mx = fmaxf(mx, vals[u]); }
    __shared__ float red[256];
    red[t] = mx; __syncthreads();
    for (int o = 128; o > 0; o >>= 1) { if (t < o) red[t] = fmaxf(red[t], red[t + o]); __syncthreads(); }
    mx = red[0]; __syncthreads();
    float s = 0.f;
    #pragma unroll
    for (int u = 0; u < 16; u++) { vals[u] = expf(vals[u] - mx); s += vals[u]; }
    red[t] = s; __syncthreads();
    for (int o = 128; o > 0; o >>= 1) { if (t < o) red[t] += red[t + o]; __syncthreads(); }
    float inv = 1.f / red[0];
    #pragma unroll
    for (int u = 0; u < 16; u++) p[t + u * 256] = vals[u] * inv;
}

__global__ void colsum_kernel(const float* __restrict__ S, float* __restrict__ csum)
{
    int j = blockIdx.x * 256 + threadIdx.x;
    int bh = blockIdx.y;
    const float* p = S + (long long)bh * NQ * NK + j;
    float s = 0.f;
    for (int i = 0; i < NQ; i++) s += p[(long long)i * NK];
    csum[bh * NK + j] = s;
}

__global__ void gelu_kernel(float* __restrict__ h, long long n)
{
    long long idx = (long long)blockIdx.x * blockDim.x + threadIdx.x;
    if (idx >= n) return;
    float v = h[idx];
    h[idx] = 0.5f * v * (1.f + erff(v * 0.70710678118654752f));
}

__global__ void out_x_kernel(float* __restrict__ out, const float* __restrict__ x)
{
    int idx = blockIdx.x * blockDim.x + threadIdx.x;
    if (idx >= MROWS * Dm) return;
    out[idx] = x[idx];
}

// outq = outk / (csum + eps); outk already holds the final softmax
__global__ void out_q_kernel(float* __restrict__ outq, const float* __restrict__ outk,
                             const float* __restrict__ csum)
{
    long long idx = (long long)blockIdx.x * blockDim.x + threadIdx.x;
    if (idx >= (long long)BH * NQ * NK) return;
    int j = (int)(idx % NK);
    int bh = (int)(idx / ((long long)NQ * NK));
    outq[idx] = outk[idx] / (csum[bh * NK + j] + EPSF);
}

// ---------------- host ----------------
extern "C" void kernel_launch(void* const* d_in, const int* in_sizes, int n_in,
                              void* d_out, int out_size)
{
    const float* x      = (const float*)d_in[0];
    const float* conv_w = (const float*)d_in[1];
    const float* conv_b = (const float*)d_in[2];
    const float* kv_w   = (const float*)d_in[3];
    const float* kv_b   = (const float*)d_in[4];
    const float* q_w    = (const float*)d_in[5];
    const float* q_b    = (const float*)d_in[6];
    const float* w1     = (const float*)d_in[7];
    const float* b1m    = (const float*)d_in[8];
    const float* w2     = (const float*)d_in[9];
    const float* b2m    = (const float*)d_in[10];
    const float* g1     = (const float*)d_in[11];
    const float* b1g    = (const float*)d_in[12];
    const float* g2     = (const float*)d_in[13];
    const float* b2g    = (const float*)d_in[14];
    const float* g3     = (const float*)d_in[15];
    const float* b3g    = (const float*)d_in[16];
    const float* temp   = (const float*)d_in[17];
    const float* freqs  = (const float*)d_in[18];
    float* out = (float*)d_out;

    static float *p_col=0,*p_convC=0,*p_xout=0,*p_kv=0,*p_k=0,*p_vT=0,*p_vs=0,*p_q=0,
                 *p_qlin=0,*p_attn=0,*p_csum=0,*p_upd=0,*p_h1=0,*p_h2=0,
                 *p_kvwT=0,*p_qwT=0,*p_w1T=0,*p_w2T=0;
    if (!p_col) {
        void* t;
        cudaGetSymbolAddress(&t, g_col);   p_col   = (float*)t;
        cudaGetSymbolAddress(&t, g_convC); p_convC = (float*)t;
        cudaGetSymbolAddress(&t, g_xout);  p_xout  = (float*)t;
        cudaGetSymbolAddress(&t, g_kv);    p_kv    = (float*)t;
        cudaGetSymbolAddress(&t, g_k);     p_k     = (float*)t;
        cudaGetSymbolAddress(&t, g_vT);    p_vT    = (float*)t;
        cudaGetSymbolAddress(&t, g_vs);    p_vs    = (float*)t;
        cudaGetSymbolAddress(&t, g_q);     p_q     = (float*)t;
        cudaGetSymbolAddress(&t, g_qlin);  p_qlin  = (float*)t;
        cudaGetSymbolAddress(&t, g_attn);  p_attn  = (float*)t;
        cudaGetSymbolAddress(&t, g_csum);  p_csum  = (float*)t;
        cudaGetSymbolAddress(&t, g_upd);   p_upd   = (float*)t;
        cudaGetSymbolAddress(&t, g_h1);    p_h1    = (float*)t;
        cudaGetSymbolAddress(&t, g_h2);    p_h2    = (float*)t;
        cudaGetSymbolAddress(&t, g_kvwT);  p_kvwT  = (float*)t;
        cudaGetSymbolAddress(&t, g_qwT);   p_qwT   = (float*)t;
        cudaGetSymbolAddress(&t, g_w1T);   p_w1T   = (float*)t;
        cudaGetSymbolAddress(&t, g_w2T);   p_w2T   = (float*)t;
    }

    float* outq = out + (long long)MROWS * Dm;
    float* outk = outq + (long long)BH * NQ * NK;

    const int TB = 256;
    transpose_kn<<<(Dm*2*Dm + TB-1)/TB, TB>>>(kv_w, p_kvwT, Dm, 2*Dm);
    transpose_kn<<<(Dm*Dm   + TB-1)/TB, TB>>>(q_w,  p_qwT,  Dm, Dm);
    transpose_kn<<<(Dm*4*Dm + TB-1)/TB, TB>>>(w1,   p_w1T,  Dm, 4*Dm);
    transpose_kn<<<(4*Dm*Dm + TB-1)/TB, TB>>>(w2,   p_w2T,  4*Dm, Dm);

    // conv: im2col + split-K tf32 GEMM (C pre-filled with bias)
    im2col_kernel<<<(int)(((long long)MROWS*KCOL + TB-1)/TB), TB>>>(x, p_col);
    fill_bias_kernel<<<(MROWS*Dm + TB-1)/TB, TB>>>(p_convC, conv_b, (long long)MROWS*Dm, Dm);
    gemm_nt_tf32<<<dim3(6, 8, 8), 256>>>(p_col, conv_w, p_convC, (const float*)0,
                                         MROWS, Dm, KCOL, 8, 0, 0, 0);
    ln_kernel<<<MROWS, 128>>>(p_convC, g1, b1g, p_xout, 0, 0);

    // loop-invariant kv / k / vT
    gemm_nt_tf32<<<dim3(12, 64, 1), 256>>>(x, p_kvwT, p_kv, kv_b,
                                           NTOK, 2*Dm, Dm, 1, 0, 0, 0);
    rose_kernel<<<(BH*NK + 127)/128, 128>>>(p_kv, 2*Dm, 0, freqs, temp, p_k, NK, GWc, 1.0f);
    build_vT_kernel<<<(int)(((long long)BH*HDc*NK + TB-1)/TB), TB>>>(p_kv, p_vT);

    for (int it = 0; it < ITERS; ++it) {
        float* S = (it == ITERS - 1) ? outk : p_attn;   // last iter: write into output
        gemm_nt_tf32<<<dim3(6, 8, 1), 256>>>(p_xout, p_qwT, p_qlin, q_b,
                                             MROWS, Dm, Dm, 1, 0, 0, 0);
        rose_kernel<<<(BH*NQ + 127)/128, 128>>>(p_qlin, Dm, 0, freqs, (const float*)0, p_q, NQ, QG, 3.0f);
        gemm_nt_tf32<<<dim3(64, 4, BH), 256>>>(p_q, p_k, S, (const float*)0,
                                               NQ, NK, HDc, 1,
                                               (long long)NQ*HDc, (long long)NK*HDc, (long long)NQ*NK);
        softmax_kernel<<<BH*NQ, 256>>>(S);
        colsum_kernel<<<dim3(NK/256, BH), 256>>>(S, p_csum);
        vscale_kernel<<<(int)(((long long)BH*HDc*NK + TB-1)/TB), TB>>>(p_vT, p_csum, p_vs);
        cudaMemsetAsync(p_upd, 0, (size_t)BH * NQ * HDc * sizeof(float));
        gemm_nt_tf32<<<dim3(1, 4, BH * 4), 256>>>(S, p_vs, p_upd, (const float*)0,
                                                  NQ, HDc, NK, 4,
                                                  (long long)NQ*NK, (long long)HDc*NK, (long long)NQ*HDc);
        ln_kernel<<<MROWS, 128>>>(p_upd, g2, b2g, p_xout, 1, 1);
        gemm_nt_tf32<<<dim3(24, 8, 1), 256>>>(p_xout, p_w1T, p_h1, b1m,
                                              MROWS, 4*Dm, Dm, 1, 0, 0, 0);
        gelu_kernel<<<(int)(((long long)MROWS*4*Dm + TB-1)/TB), TB>>>(p_h1, (long long)MROWS*4*Dm);
        gemm_nt_tf32<<<dim3(6, 8, 1), 256>>>(p_h1, p_w2T, p_h2, b2m,
                                             MROWS, Dm, 4*Dm, 1, 0, 0, 0);
        ln_kernel<<<MROWS, 128>>>(p_h2, g3, b3g, p_xout, 0, 1);
    }

    out_x_kernel<<<(MROWS*Dm + TB-1)/TB, TB>>>(out, p_xout);
    out_q_kernel<<<(int)(((long long)BH*NQ*NK + TB-1)/TB), TB>>>(outq, outk, p_csum);
    (void)in_sizes; (void)n_in; (void)out_size;
}

// round 3
// speedup vs baseline: 2.0528x; 1.3059x over previous
#include <cuda_runtime.h>
#include <math.h>
#include <stdint.h>

// ---------------- problem constants ----------------
#define Bb    2
#define GHc   64
#define GWc   64
#define Dm    384
#define Hh    12
#define HDc   32
#define QG    22
#define NQ    484
#define NK    4096
#define BH    24
#define ITERS 3
#define KCOL  18816          // 49*384, reordered (kh,kw,ci)
#define MROWS 968
#define NTOK  8192
#define LN_EPSF 1e-5f
#define EPSF  1.1920929e-07f

// ---------------- scratch ----------------
__device__ float g_convR[Dm * KCOL];       // reordered conv weights (28.9MB)
__device__ float g_convC[MROWS * Dm];
__device__ float g_xout[MROWS * Dm];
__device__ float g_kv[NTOK * 2 * Dm];
__device__ float g_k[BH * NK * HDc];
__device__ float g_vT[BH * HDc * NK];
__device__ float g_vs[BH * HDc * NK];
__device__ float g_q[BH * NQ * HDc];
__device__ float g_qlin[MROWS * Dm];
__device__ float g_attn[(long long)BH * NQ * NK];
__device__ float g_csum[BH * NK];
__device__ float g_upd[BH * NQ * HDc];
__device__ float g_h1[MROWS * 4 * Dm];
__device__ float g_h2[MROWS * Dm];
__device__ float g_kvwT[2 * Dm * Dm];
__device__ float g_qwT[Dm * Dm];
__device__ float g_w1T[4 * Dm * Dm];
__device__ float g_w2T[Dm * 4 * Dm];

__device__ __forceinline__ unsigned f2tf(float f) {
    unsigned u;
    asm("cvt.rna.tf32.f32 %0, %1;" : "=r"(u) : "f"(f));
    return u;
}
__device__ __forceinline__ void cpa16(uint32_t s, const float* g, int sz) {
    asm volatile("cp.async.cg.shared.global [%0], [%1], 16, %2;" :: "r"(s), "l"(g), "r"(sz));
}
__device__ __forceinline__ void cpa_commit() { asm volatile("cp.async.commit_group;"); }
__device__ __forceinline__ void cpa_wait0()  { asm volatile("cp.async.wait_group 0;" ::: "memory"); }

// ================= pipelined TF32 NT GEMM =================
// C[M,N] = A[M,K]*B[N,K]^T (+bias). CONV: A is implicit im2col of x
// (channels-last, weights reordered (kh,kw,ci)). GELU: apply gelu in epilogue.
// nsplit>1: split-K, atomicAdd into pre-initialized C.
// Tile 128x64x16, 256 thr = 8 warps (4m x 2n), double-buffered cp.async.
template<bool CONV, bool GELU>
__global__ void __launch_bounds__(256)
gemm_pipe(const float* __restrict__ A, const float* __restrict__ Bp,
          float* __restrict__ C, const float* __restrict__ bias,
          int M, int N, int K, int nsplit,
          long long sA, long long sB, long long sC)
{
    const int bz = blockIdx.z;
    const int batch = bz / nsplit, chunk = bz - batch * nsplit;
    const int Kc = K / nsplit;
    const int ckbase = chunk * Kc;
    if (!CONV) A += (long long)batch * sA + ckbase;
    Bp += (long long)batch * sB + ckbase;
    C  += (long long)batch * sC;

    __shared__ float As[2][128][20];
    __shared__ float Bs[2][64][20];
    const uint32_t sa = (uint32_t)__cvta_generic_to_shared(&As[0][0][0]);
    const uint32_t sb = (uint32_t)__cvta_generic_to_shared(&Bs[0][0][0]);

    const int t = threadIdx.x;
    const int lane = t & 31, warp = t >> 5;
    const int g = lane >> 2, tig = lane & 3;
    const int wm = warp >> 1, wn = warp & 1;
    const int m0 = blockIdx.y * 128, n0 = blockIdx.x * 64;

    // per-thread A-row geometry (2 rows), fixed across K loop
    int arow[2], acol4;
    int cb_[2], coh_[2], cow_[2];
    bool rok_[2];
    #pragma unroll
    for (int i = 0; i < 2; i++) {
        int id = t + i * 256;
        arow[i] = id >> 2;
        int gm = m0 + arow[i];
        rok_[i] = gm < M;
        if (CONV) {
            int gmc = rok_[i] ? gm : 0;
            cb_[i] = gmc / NQ;
            int nq = gmc - cb_[i] * NQ;
            coh_[i] = nq / QG;
            cow_[i] = nq - coh_[i] * QG;
        }
    }
    acol4 = (t & 3) << 2;
    const int brow = t >> 2;
    const int gn = n0 + brow;
    const bool bok = gn < N;
    const float* bptr_base = Bp + (long long)(bok ? gn : 0) * K;

    const int ntiles = Kc / 16;

    // prefetch macro
    auto prefetch = [&](int kt, int buf) {
        const int k0 = kt * 16;
        #pragma unroll
        for (int i = 0; i < 2; i++) {
            const float* gp; int sz;
            if (CONV) {
                int kg = ckbase + k0 + acol4;
                int kpos = kg / Dm, ci = kg - kpos * Dm;
                int kh = kpos / 7, kw = kpos - kh * 7;
                int ih = coh_[i] * 3 - 3 + kh, iw = cow_[i] * 3 - 3 + kw;
                bool ok = rok_[i] && (unsigned)ih < (unsigned)GHc && (unsigned)iw < (unsigned)GWc;
                gp = A + (ok ? ((long long)(cb_[i] * NK + ih * GWc + iw) * Dm + ci) : 0);
                sz = ok ? 16 : 0;
            } else {
                int gm = m0 + arow[i];
                bool ok = gm < M;
                gp = A + (long long)(ok ? gm : 0) * K + k0 + acol4;
                sz = ok ? 16 : 0;
            }
            cpa16(sa + (((buf * 128 + arow[i]) * 20 + acol4) << 2), gp, sz);
        }
        cpa16(sb + (((buf * 64 + brow) * 20 + acol4) << 2),
              bptr_base + k0 + acol4, bok ? 16 : 0);
        cpa_commit();
    };

    float acc[2][4][4];
    #pragma unroll
    for (int a = 0; a < 2; a++)
        #pragma unroll
        for (int b = 0; b < 4; b++)
            #pragma unroll
            for (int c = 0; c < 4; c++) acc[a][b][c] = 0.f;

    prefetch(0, 0);
    for (int kt = 0; kt < ntiles; kt++) {
        const int buf = kt & 1;
        cpa_wait0();
        __syncthreads();
        if (kt + 1 < ntiles) prefetch(kt + 1, (kt + 1) & 1);

        #pragma unroll
        for (int ks = 0; ks < 16; ks += 8) {
            unsigned af[2][4], bf[4][2];
            #pragma unroll
            for (int mt = 0; mt < 2; mt++) {
                int r = wm * 32 + mt * 16 + g;
                af[mt][0] = f2tf(As[buf][r][ks + tig]);
                af[mt][1] = f2tf(As[buf][r + 8][ks + tig]);
                af[mt][2] = f2tf(As[buf][r][ks + tig + 4]);
                af[mt][3] = f2tf(As[buf][r + 8][ks + tig + 4]);
            }
            #pragma unroll
            for (int nt = 0; nt < 4; nt++) {
                int r = wn * 32 + nt * 8 + g;
                bf[nt][0] = f2tf(Bs[buf][r][ks + tig]);
                bf[nt][1] = f2tf(Bs[buf][r][ks + tig + 4]);
            }
            #pragma unroll
            for (int mt = 0; mt < 2; mt++)
                #pragma unroll
                for (int nt = 0; nt < 4; nt++)
                    asm volatile(
                        "mma.sync.aligned.m16n8k8.row.col.f32.tf32.tf32.f32 "
                        "{%0,%1,%2,%3},{%4,%5,%6,%7},{%8,%9},{%0,%1,%2,%3};"
                        : "+f"(acc[mt][nt][0]), "+f"(acc[mt][nt][1]),
                          "+f"(acc[mt][nt][2]), "+f"(acc[mt][nt][3])
                        : "r"(af[mt][0]), "r"(af[mt][1]), "r"(af[mt][2]), "r"(af[mt][3]),
                          "r"(bf[nt][0]), "r"(bf[nt][1]));
        }
        __syncthreads();
    }

    const bool atomic = nsplit > 1;
    #pragma unroll
    for (int mt = 0; mt < 2; mt++) {
        #pragma unroll
        for (int nt = 0; nt < 4; nt++) {
            int m = m0 + wm * 32 + mt * 16 + g;
            int n = n0 + wn * 32 + nt * 8 + 2 * tig;
            if (n >= N) continue;
            float bv0 = bias ? bias[n] : 0.f;
            float bv1 = bias ? bias[n + 1] : 0.f;
            #pragma unroll
            for (int half = 0; half < 2; half++) {
                int mm = m + half * 8;
                if (mm >= M) continue;
                float v0 = acc[mt][nt][half * 2 + 0];
                float v1 = acc[mt][nt][half * 2 + 1];
                if (atomic) {
                    atomicAdd(&C[(long long)mm * N + n],     v0);
                    atomicAdd(&C[(long long)mm * N + n + 1], v1);
                } else {
                    v0 += bv0; v1 += bv1;
                    if (GELU) {
                        v0 = 0.5f * v0 * (1.f + erff(v0 * 0.70710678118654752f));
                        v1 = 0.5f * v1 * (1.f + erff(v1 * 0.70710678118654752f));
                    }
                    *(float2*)(C + (long long)mm * N + n) = make_float2(v0, v1);
                }
            }
        }
    }
}

// ---------------- helpers ----------------
__global__ void reorder_convw(const float* __restrict__ W, float* __restrict__ R)
{
    long long idx = (long long)blockIdx.x * blockDim.x + threadIdx.x;
    if (idx >= (long long)Dm * KCOL) return;
    int n = (int)(idx / KCOL), r = (int)(idx % KCOL);
    int kpos = r / Dm, ci = r - kpos * Dm;
    R[idx] = W[((long long)n * Dm + ci) * 49 + kpos];
}

__global__ void transpose_kn(const float* __restrict__ W, float* __restrict__ WT, int K, int N)
{
    long long idx = (long long)blockIdx.x * blockDim.x + threadIdx.x;
    if (idx >= (long long)K * N) return;
    int n = (int)(idx % N), k = (int)(idx / N);
    WT[(long long)n * K + k] = W[idx];
}

__global__ void fill_bias_kernel(float* __restrict__ C, const float* __restrict__ b, long long total, int N)
{
    long long idx = (long long)blockIdx.x * blockDim.x + threadIdx.x;
    if (idx >= total) return;
    C[idx] = b[idx % N];
}

__global__ void ln_kernel(const float* __restrict__ src, const float* __restrict__ gam,
                          const float* __restrict__ bet, float* __restrict__ dst,
                          int gather_heads, int add_to)
{
    int row = blockIdx.x;
    int t = threadIdx.x;
    __shared__ float red[128];
    int b = row / NQ, i = row % NQ;
    float v[3];
    #pragma unroll
    for (int u = 0; u < 3; u++) {
        int c = t + u * 128;
        if (gather_heads) {
            int h = c >> 5, d = c & 31;
            v[u] = src[(((long long)(b * Hh + h)) * NQ + i) * HDc + d];
        } else {
            v[u] = src[(long long)row * Dm + c];
        }
    }
    float s = v[0] + v[1] + v[2];
    red[t] = s; __syncthreads();
    for (int o = 64; o > 0; o >>= 1) { if (t < o) red[t] += red[t + o]; __syncthreads(); }
    float mu = red[0] * (1.f / 384.f);
    __syncthreads();
    float sq = 0.f;
    #pragma unroll
    for (int u = 0; u < 3; u++) { float d = v[u] - mu; sq += d * d; }
    red[t] = sq; __syncthreads();
    for (int o = 64; o > 0; o >>= 1) { if (t < o) red[t] += red[t + o]; __syncthreads(); }
    float rstd = rsqrtf(red[0] * (1.f / 384.f) + LN_EPSF);
    #pragma unroll
    for (int u = 0; u < 3; u++) {
        int c = t + u * 128;
        float y = (v[u] - mu) * rstd * gam[c] + bet[c];
        long long o = (long long)row * Dm + c;
        if (add_to) dst[o] += y; else dst[o] = y;
    }
}

__global__ void rose_kernel(const float* __restrict__ src, int srow, int soff,
                            const float* __restrict__ freqs, const float* __restrict__ tempp,
                            float* __restrict__ dst, int Ntok, int gw, float sp)
{
    int idx = blockIdx.x * blockDim.x + threadIdx.x;
    if (idx >= Bb * Hh * Ntok) return;
    int n = idx % Ntok, bh = idx / Ntok;
    int h = bh % Hh, b = bh / Hh;
    const float* row = src + ((long long)(b * Ntok + n)) * srow + soff + h * HDc;
    float c0 = (float)(n / gw) * sp;
    float c1 = (float)(n % gw) * sp;
    float sc = tempp ? tempp[0] : 1.f;
    float* o = dst + (long long)idx * HDc;
    #pragma unroll
    for (int tt = 0; tt < 8; tt++) {
        float f = freqs[h * 8 + tt];
        float ang = ((tt < 4) ? c0 : c1) * f;
        float sn, cs;
        sincosf(ang, &sn, &cs);
        float x1 = row[2 * tt], x2 = row[2 * tt + 1];
        o[2 * tt]     = sc * (x1 * cs - x2 * sn);
        o[2 * tt + 1] = sc * (x1 * sn + x2 * cs);
    }
    #pragma unroll
    for (int d = 16; d < 32; d++) o[d] = sc * row[d];
}

__global__ void build_vT_kernel(const float* __restrict__ kv, float* __restrict__ vT)
{
    long long idx = (long long)blockIdx.x * blockDim.x + threadIdx.x;
    if (idx >= (long long)BH * HDc * NK) return;
    int j = (int)(idx % NK);
    int r = (int)(idx / NK);
    int d = r % HDc, bh = r / HDc;
    int h = bh % Hh, b = bh / Hh;
    vT[idx] = kv[((long long)(b * NK + j)) * (2 * Dm) + Dm + h * HDc + d];
}

__global__ void vscale_kernel(const float* __restrict__ vT, const float* __restrict__ csum,
                              float* __restrict__ vs)
{
    long long idx = (long long)blockIdx.x * blockDim.x + threadIdx.x;
    if (idx >= (long long)BH * HDc * NK) return;
    int j = (int)(idx % NK);
    int bh = (int)(idx / ((long long)HDc * NK));
    vs[idx] = vT[idx] / (csum[bh * NK + j] + EPSF);
}

__global__ void softmax_kernel(float* __restrict__ S)
{
    long long row = blockIdx.x;
    float* p = S + row * NK;
    int t = threadIdx.x;
    float vals[16];
    float mx = -INFINITY;
    #pragma unroll
    for (int u = 0; u < 16; u++) { vals[u] = p[t + u * 256]; mx = fmaxf(mx, vals[u]); }
    __shared__ float red[256];
    red[t] = mx; __syncthreads();
    for (int o = 128; o > 0; o >>= 1) { if (t < o) red[t] = fmaxf(red[t], red[t + o]); __syncthreads(); }
    mx = red[0]; __syncthreads();
    float s = 0.f;
    #pragma unroll
    for (int u = 0; u < 16; u++) { vals[u] = __expf(vals[u] - mx); s += vals[u]; }
    red[t] = s; __syncthreads();
    for (int o = 128; o > 0; o >>= 1) { if (t < o) red[t] += red[t + o]; __syncthreads(); }
    float inv = 1.f / red[0];
    #pragma unroll
    for (int u = 0; u < 16; u++) p[t + u * 256] = vals[u] * inv;
}

__global__ void colsum_kernel(const float* __restrict__ S, float* __restrict__ csum)
{
    int j = blockIdx.x * 256 + threadIdx.x;
    int bh = blockIdx.y;
    const float* p = S + (long long)bh * NQ * NK + j;
    float s = 0.f;
    for (int i = 0; i < NQ; i++) s += p[(long long)i * NK];
    csum[bh * NK + j] = s;
}

__global__ void out_x_kernel(float* __restrict__ out, const float* __restrict__ x)
{
    int idx = blockIdx.x * blockDim.x + threadIdx.x;
    if (idx >= MROWS * Dm) return;
    out[idx] = x[idx];
}

__global__ void out_q_kernel(float* __restrict__ outq, const float* __restrict__ outk,
                             const float* __restrict__ csum)
{
    long long idx = (long long)blockIdx.x * blockDim.x + threadIdx.x;
    if (idx >= (long long)BH * NQ * NK) return;
    int j = (int)(idx % NK);
    int bh = (int)(idx / ((long long)NQ * NK));
    outq[idx] = outk[idx] / (csum[bh * NK + j] + EPSF);
}

// ---------------- host ----------------
extern "C" void kernel_launch(void* const* d_in, const int* in_sizes, int n_in,
                              void* d_out, int out_size)
{
    const float* x      = (const float*)d_in[0];
    const float* conv_w = (const float*)d_in[1];
    const float* conv_b = (const float*)d_in[2];
    const float* kv_w   = (const float*)d_in[3];
    const float* kv_b   = (const float*)d_in[4];
    const float* q_w    = (const float*)d_in[5];
    const float* q_b    = (const float*)d_in[6];
    const float* w1     = (const float*)d_in[7];
    const float* b1m    = (const float*)d_in[8];
    const float* w2     = (const float*)d_in[9];
    const float* b2m    = (const float*)d_in[10];
    const float* g1     = (const float*)d_in[11];
    const float* b1g    = (const float*)d_in[12];
    const float* g2     = (const float*)d_in[13];
    const float* b2g    = (const float*)d_in[14];
    const float* g3     = (const float*)d_in[15];
    const float* b3g    = (const float*)d_in[16];
    const float* temp   = (const float*)d_in[17];
    const float* freqs  = (const float*)d_in[18];
    float* out = (float*)d_out;

    static float *p_convR=0,*p_convC=0,*p_xout=0,*p_kv=0,*p_k=0,*p_vT=0,*p_vs=0,*p_q=0,
                 *p_qlin=0,*p_attn=0,*p_csum=0,*p_upd=0,*p_h1=0,*p_h2=0,
                 *p_kvwT=0,*p_qwT=0,*p_w1T=0,*p_w2T=0;
    if (!p_convR) {
        void* t;
        cudaGetSymbolAddress(&t, g_convR); p_convR = (float*)t;
        cudaGetSymbolAddress(&t, g_convC); p_convC = (float*)t;
        cudaGetSymbolAddress(&t, g_xout);  p_xout  = (float*)t;
        cudaGetSymbolAddress(&t, g_kv);    p_kv    = (float*)t;
        cudaGetSymbolAddress(&t, g_k);     p_k     = (float*)t;
        cudaGetSymbolAddress(&t, g_vT);    p_vT    = (float*)t;
        cudaGetSymbolAddress(&t, g_vs);    p_vs    = (float*)t;
        cudaGetSymbolAddress(&t, g_q);     p_q     = (float*)t;
        cudaGetSymbolAddress(&t, g_qlin);  p_qlin  = (float*)t;
        cudaGetSymbolAddress(&t, g_attn);  p_attn  = (float*)t;
        cudaGetSymbolAddress(&t, g_csum);  p_csum  = (float*)t;
        cudaGetSymbolAddress(&t, g_upd);   p_upd   = (float*)t;
        cudaGetSymbolAddress(&t, g_h1);    p_h1    = (float*)t;
        cudaGetSymbolAddress(&t, g_h2);    p_h2    = (float*)t;
        cudaGetSymbolAddress(&t, g_kvwT);  p_kvwT  = (float*)t;
        cudaGetSymbolAddress(&t, g_qwT);   p_qwT   = (float*)t;
        cudaGetSymbolAddress(&t, g_w1T);   p_w1T   = (float*)t;
        cudaGetSymbolAddress(&t, g_w2T);   p_w2T   = (float*)t;
    }

    float* outq = out + (long long)MROWS * Dm;
    float* outk = outq + (long long)BH * NQ * NK;

    const int TB = 256;
    reorder_convw<<<(int)(((long long)Dm*KCOL + TB-1)/TB), TB>>>(conv_w, p_convR);
    transpose_kn<<<(Dm*2*Dm + TB-1)/TB, TB>>>(kv_w, p_kvwT, Dm, 2*Dm);
    transpose_kn<<<(Dm*Dm   + TB-1)/TB, TB>>>(q_w,  p_qwT,  Dm, Dm);
    transpose_kn<<<(Dm*4*Dm + TB-1)/TB, TB>>>(w1,   p_w1T,  Dm, 4*Dm);
    transpose_kn<<<(4*Dm*Dm + TB-1)/TB, TB>>>(w2,   p_w2T,  4*Dm, Dm);

    // conv: implicit im2col + split-K tf32 GEMM (C pre-filled with bias)
    fill_bias_kernel<<<(MROWS*Dm + TB-1)/TB, TB>>>(p_convC, conv_b, (long long)MROWS*Dm, Dm);
    gemm_pipe<true,false><<<dim3(6, 8, 8), 256>>>(x, p_convR, p_convC, (const float*)0,
                                                  MROWS, Dm, KCOL, 8, 0, 0, 0);
    ln_kernel<<<MROWS, 128>>>(p_convC, g1, b1g, p_xout, 0, 0);

    // loop-invariant kv / k / vT
    gemm_pipe<false,false><<<dim3(12, 64, 1), 256>>>(x, p_kvwT, p_kv, kv_b,
                                                     NTOK, 2*Dm, Dm, 1, 0, 0, 0);
    rose_kernel<<<(BH*NK + 127)/128, 128>>>(p_kv, 2*Dm, 0, freqs, temp, p_k, NK, GWc, 1.0f);
    build_vT_kernel<<<(int)(((long long)BH*HDc*NK + TB-1)/TB), TB>>>(p_kv, p_vT);

    for (int it = 0; it < ITERS; ++it) {
        const bool last = (it == ITERS - 1);
        float* S = last ? outk : p_attn;
        gemm_pipe<false,false><<<dim3(6, 8, 1), 256>>>(p_xout, p_qwT, p_qlin, q_b,
                                                       MROWS, Dm, Dm, 1, 0, 0, 0);
        rose_kernel<<<(BH*NQ + 127)/128, 128>>>(p_qlin, Dm, 0, freqs, (const float*)0, p_q, NQ, QG, 3.0f);
        gemm_pipe<false,false><<<dim3(64, 4, BH), 256>>>(p_q, p_k, S, (const float*)0,
                                                         NQ, NK, HDc, 1,
                                                         (long long)NQ*HDc, (long long)NK*HDc, (long long)NQ*NK);
        softmax_kernel<<<BH*NQ, 256>>>(S);
        colsum_kernel<<<dim3(NK/256, BH), 256>>>(S, p_csum);
        cudaMemsetAsync(p_upd, 0, (size_t)BH * NQ * HDc * sizeof(float));
        if (last) {
            // attn_q output is needed anyway: compute it, then upd = outq @ vT
            out_q_kernel<<<(int)(((long long)BH*NQ*NK + TB-1)/TB), TB>>>(outq, outk, p_csum);
            gemm_pipe<false,false><<<dim3(1, 4, BH * 4), 256>>>(outq, p_vT, p_upd, (const float*)0,
                                                                NQ, HDc, NK, 4,
                                                                (long long)NQ*NK, (long long)HDc*NK, (long long)NQ*HDc);
        } else {
            vscale_kernel<<<(int)(((long long)BH*HDc*NK + TB-1)/TB), TB>>>(p_vT, p_csum, p_vs);
            gemm_pipe<false,false><<<dim3(1, 4, BH * 4), 256>>>(S, p_vs, p_upd, (const float*)0,
                                                                NQ, HDc, NK, 4,
                                                                (long long)NQ*NK, (long long)HDc*NK, (long long)NQ*HDc);
        }
        ln_kernel<<<MROWS, 128>>>(p_upd, g2, b2g, p_xout, 1, 1);
        gemm_pipe<false,true><<<dim3(24, 8, 1), 256>>>(p_xout, p_w1T, p_h1, b1m,
                                                       MROWS, 4*Dm, Dm, 1, 0, 0, 0);
        gemm_pipe<false,false><<<dim3(6, 8, 1), 256>>>(p_h1, p_w2T, p_h2, b2m,
                                                       MROWS, Dm, 4*Dm, 1, 0, 0, 0);
        ln_kernel<<<MROWS, 128>>>(p_h2, g3, b3g, p_xout, 0, 1);
    }

    out_x_kernel<<<(MROWS*Dm + TB-1)/TB, TB>>>(out, p_xout);
    (void)in_sizes; (void)n_in; (void)out_size;
}

// round 5
// speedup vs baseline: 2.3721x; 1.1555x over previous
#include <cuda_runtime.h>
#include <math.h>
#include <stdint.h>

// ---------------- problem constants ----------------
#define Bb    2
#define GHc   64
#define GWc   64
#define Dm    384
#define Hh    12
#define HDc   32
#define QG    22
#define NQ    484
#define NK    4096
#define BH    24
#define ITERS 3
#define KCOL  18816          // 49*384, reordered (kh,kw,ci)
#define MROWS 968
#define NTOK  8192
#define LN_EPSF 1e-5f
#define EPSF  1.1920929e-07f

// ---------------- scratch ----------------
__device__ float g_convR[Dm * KCOL];
__device__ float g_convC[MROWS * Dm];
__device__ float g_xout[MROWS * Dm];
__device__ float g_kv[NTOK * 2 * Dm];
__device__ float g_k[BH * NK * HDc];
__device__ float g_vT[BH * HDc * NK];
__device__ float g_vs[BH * HDc * NK];
__device__ float g_q[BH * NQ * HDc];
__device__ float g_qlin[MROWS * Dm];
__device__ float g_attn[(long long)BH * NQ * NK];
__device__ float g_csum[BH * NK];
__device__ float g_upd[BH * NQ * HDc];
__device__ float g_h1[MROWS * 4 * Dm];
__device__ float g_h2[MROWS * Dm];
__device__ float g_kvwT[2 * Dm * Dm];
__device__ float g_qwT[Dm * Dm];
__device__ float g_w1T[4 * Dm * Dm];
__device__ float g_w2T[Dm * 4 * Dm];

__device__ __forceinline__ unsigned f2tf(float f) {
    unsigned u;
    asm("cvt.rna.tf32.f32 %0, %1;" : "=r"(u) : "f"(f));
    return u;
}
__device__ __forceinline__ float tfr(float f) { return __uint_as_float(f2tf(f)); }
__device__ __forceinline__ void cpa16(uint32_t s, const float* g, int sz) {
    asm volatile("cp.async.cg.shared.global [%0], [%1], 16, %2;" :: "r"(s), "l"(g), "r"(sz));
}
__device__ __forceinline__ void cpa_commit() { asm volatile("cp.async.commit_group;"); }
__device__ __forceinline__ void cpa_wait1()  { asm volatile("cp.async.wait_group 1;" ::: "memory"); }

// ================= pipelined TF32 NT GEMM =================
// C[M,N]=A[M,K]*B[N,K]^T (+bias). B operands are pre-rounded to tf32 by their
// producers; A converted in-loop iff CVTA. CONV: implicit im2col of x.
// nsplit>1: split-K, atomicAdd into pre-initialized C (bias prefilled).
// Tile 128 x NTILE x 16, 256 thr = 8 warps (4m x 2n), 3-stage cp.async.
template<int NTILE, bool CONV, bool CVTA>
__global__ void __launch_bounds__(256)
gemm_tc(const float* __restrict__ A, const float* __restrict__ Bp,
        float* __restrict__ C, const float* __restrict__ bias,
        int M, int N, int K, int nsplit,
        long long sA, long long sB, long long sC)
{
    constexpr int WN = NTILE / 2;      // warp n-extent
    constexpr int NT = WN / 8;         // n8 tiles per warp
    extern __shared__ float smem[];
    float* As = smem;                         // [3][128][20]
    float* Bs = smem + 3 * 128 * 20;          // [3][NTILE][20]

    const int bz = blockIdx.z;
    const int batch = bz / nsplit, chunk = bz - batch * nsplit;
    const int Kc = K / nsplit;
    const int ckbase = chunk * Kc;
    if (!CONV) A += (long long)batch * sA + ckbase;
    Bp += (long long)batch * sB + ckbase;
    C  += (long long)batch * sC;

    const uint32_t sa = (uint32_t)__cvta_generic_to_shared(As);
    const uint32_t sb = (uint32_t)__cvta_generic_to_shared(Bs);

    const int t = threadIdx.x;
    const int lane = t & 31, warp = t >> 5;
    const int g = lane >> 2, tig = lane & 3;
    const int wm = warp >> 1, wn = warp & 1;
    const int m0 = blockIdx.y * 128, n0 = blockIdx.x * NTILE;
    const int acol4 = (t & 3) << 2;

    // A-row geometry (2 rows/thread)
    int arow[2]; bool rok_[2];
    int cb_[2], coh_[2], cow_[2];
    #pragma unroll
    for (int i = 0; i < 2; i++) {
        int id = t + i * 256;
        arow[i] = id >> 2;
        int gm = m0 + arow[i];
        rok_[i] = gm < M;
        if (CONV) {
            int gmc = rok_[i] ? gm : 0;
            cb_[i] = gmc / NQ;
            int nq = gmc - cb_[i] * NQ;
            coh_[i] = nq / QG;
            cow_[i] = nq - coh_[i] * QG;
        }
    }
    // B-row geometry (NTILE/64 rows/thread)
    int brow_[2]; bool bok_[2];
    #pragma unroll
    for (int i = 0; i < NTILE / 64; i++) {
        int id = t + i * 256;
        brow_[i] = id >> 2;
        bok_[i] = (n0 + brow_[i]) < N;
    }

    const int ntiles = Kc / 16;

    auto prefetch = [&](int kt, int buf) {
        if (kt < ntiles) {
            const int k0 = kt * 16;
            #pragma unroll
            for (int i = 0; i < 2; i++) {
                const float* gp; int sz;
                if (CONV) {
                    int kg = ckbase + k0 + acol4;
                    int kpos = kg / Dm, ci = kg - kpos * Dm;
                    int kh = kpos / 7, kw = kpos - kh * 7;
                    int ih = coh_[i] * 3 - 3 + kh, iw = cow_[i] * 3 - 3 + kw;
                    bool ok = rok_[i] && (unsigned)ih < (unsigned)GHc && (unsigned)iw < (unsigned)GWc;
                    gp = A + (ok ? ((long long)(cb_[i] * NK + ih * GWc + iw) * Dm + ci) : 0);
                    sz = ok ? 16 : 0;
                } else {
                    gp = A + (long long)(rok_[i] ? (m0 + arow[i]) : 0) * K + k0 + acol4;
                    sz = rok_[i] ? 16 : 0;
                }
                cpa16(sa + (((buf * 128 + arow[i]) * 20 + acol4) << 2), gp, sz);
            }
            #pragma unroll
            for (int i = 0; i < NTILE / 64; i++) {
                const float* gp = Bp + (long long)(bok_[i] ? (n0 + brow_[i]) : 0) * K + k0 + acol4;
                cpa16(sb + (((buf * NTILE + brow_[i]) * 20 + acol4) << 2), gp, bok_[i] ? 16 : 0);
            }
        }
        cpa_commit();
    };

    float acc[2][NT][4];
    #pragma unroll
    for (int a = 0; a < 2; a++)
        #pragma unroll
        for (int b = 0; b < NT; b++)
            #pragma unroll
            for (int c = 0; c < 4; c++) acc[a][b][c] = 0.f;

    prefetch(0, 0);
    prefetch(1, 1);
    for (int kt = 0; kt < ntiles; kt++) {
        const int buf = kt % 3;
        cpa_wait1();
        __syncthreads();
        prefetch(kt + 2, (kt + 2) % 3);

        const float* as0 = As + buf * (128 * 20);
        const float* bs0 = Bs + buf * (NTILE * 20);
        #pragma unroll
        for (int ks = 0; ks < 16; ks += 8) {
            unsigned af[2][4], bf[NT][2];
            #pragma unroll
            for (int mt = 0; mt < 2; mt++) {
                const float* ar = as0 + (wm * 32 + mt * 16 + g) * 20;
                float a0 = ar[ks + tig],       a1 = ar[160 + ks + tig];
                float a2 = ar[ks + tig + 4],   a3 = ar[160 + ks + tig + 4];
                if (CVTA) {
                    af[mt][0] = f2tf(a0); af[mt][1] = f2tf(a1);
                    af[mt][2] = f2tf(a2); af[mt][3] = f2tf(a3);
                } else {
                    af[mt][0] = __float_as_uint(a0); af[mt][1] = __float_as_uint(a1);
                    af[mt][2] = __float_as_uint(a2); af[mt][3] = __float_as_uint(a3);
                }
            }
            #pragma unroll
            for (int nt = 0; nt < NT; nt++) {
                const float* br = bs0 + (wn * WN + nt * 8 + g) * 20;
                bf[nt][0] = __float_as_uint(br[ks + tig]);
                bf[nt][1] = __float_as_uint(br[ks + tig + 4]);
            }
            #pragma unroll
            for (int mt = 0; mt < 2; mt++)
                #pragma unroll
                for (int nt = 0; nt < NT; nt++)
                    asm volatile(
                        "mma.sync.aligned.m16n8k8.row.col.f32.tf32.tf32.f32 "
                        "{%0,%1,%2,%3},{%4,%5,%6,%7},{%8,%9},{%0,%1,%2,%3};"
                        : "+f"(acc[mt][nt][0]), "+f"(acc[mt][nt][1]),
                          "+f"(acc[mt][nt][2]), "+f"(acc[mt][nt][3])
                        : "r"(af[mt][0]), "r"(af[mt][1]), "r"(af[mt][2]), "r"(af[mt][3]),
                          "r"(bf[nt][0]), "r"(bf[nt][1]));
        }
        __syncthreads();
    }

    const bool atomic = nsplit > 1;
    #pragma unroll
    for (int mt = 0; mt < 2; mt++) {
        #pragma unroll
        for (int nt = 0; nt < NT; nt++) {
            int m = m0 + wm * 32 + mt * 16 + g;
            int n = n0 + wn * WN + nt * 8 + 2 * tig;
            if (n >= N) continue;
            float bv0 = bias ? bias[n] : 0.f;
            float bv1 = bias ? bias[n + 1] : 0.f;
            #pragma unroll
            for (int half = 0; half < 2; half++) {
                int mm = m + half * 8;
                if (mm >= M) continue;
                float v0 = acc[mt][nt][half * 2 + 0];
                float v1 = acc[mt][nt][half * 2 + 1];
                if (atomic) {
                    atomicAdd(&C[(long long)mm * N + n],     v0);
                    atomicAdd(&C[(long long)mm * N + n + 1], v1);
                } else {
                    *(float2*)(C + (long long)mm * N + n) = make_float2(v0 + bv0, v1 + bv1);
                }
            }
        }
    }
}

// ---------------- helpers ----------------
__global__ void reorder_convw(const float* __restrict__ W, float* __restrict__ R)
{
    long long idx = (long long)blockIdx.x * blockDim.x + threadIdx.x;
    if (idx >= (long long)Dm * KCOL) return;
    int n = (int)(idx / KCOL), r = (int)(idx % KCOL);
    int kpos = r / Dm, ci = r - kpos * Dm;
    R[idx] = tfr(W[((long long)n * Dm + ci) * 49 + kpos]);
}

__global__ void transpose_kn(const float* __restrict__ W, float* __restrict__ WT, int K, int N)
{
    long long idx = (long long)blockIdx.x * blockDim.x + threadIdx.x;
    if (idx >= (long long)K * N) return;
    int n = (int)(idx % N), k = (int)(idx / N);
    WT[(long long)n * K + k] = tfr(W[idx]);
}

__global__ void fill_bias_kernel(float* __restrict__ C, const float* __restrict__ b, long long total, int N)
{
    long long idx = (long long)blockIdx.x * blockDim.x + threadIdx.x;
    if (idx >= total) return;
    C[idx] = b[idx % N];
}

__global__ void ln_kernel(const float* __restrict__ src, const float* __restrict__ gam,
                          const float* __restrict__ bet, float* __restrict__ dst,
                          int gather_heads, int add_to)
{
    int row = blockIdx.x;
    int t = threadIdx.x;
    __shared__ float red[128];
    int b = row / NQ, i = row % NQ;
    float v[3];
    #pragma unroll
    for (int u = 0; u < 3; u++) {
        int c = t + u * 128;
        if (gather_heads) {
            int h = c >> 5, d = c & 31;
            v[u] = src[(((long long)(b * Hh + h)) * NQ + i) * HDc + d];
        } else {
            v[u] = src[(long long)row * Dm + c];
        }
    }
    float s = v[0] + v[1] + v[2];
    red[t] = s; __syncthreads();
    for (int o = 64; o > 0; o >>= 1) { if (t < o) red[t] += red[t + o]; __syncthreads(); }
    float mu = red[0] * (1.f / 384.f);
    __syncthreads();
    float sq = 0.f;
    #pragma unroll
    for (int u = 0; u < 3; u++) { float d = v[u] - mu; sq += d * d; }
    red[t] = sq; __syncthreads();
    for (int o = 64; o > 0; o >>= 1) { if (t < o) red[t] += red[t + o]; __syncthreads(); }
    float rstd = rsqrtf(red[0] * (1.f / 384.f) + LN_EPSF);
    #pragma unroll
    for (int u = 0; u < 3; u++) {
        int c = t + u * 128;
        float y = (v[u] - mu) * rstd * gam[c] + bet[c];
        long long o = (long long)row * Dm + c;
        if (add_to) dst[o] += y; else dst[o] = y;
    }
}

// rose: writes tf32-rounded outputs (consumed as mma operands only)
__global__ void rose_kernel(const float* __restrict__ src, int srow, int soff,
                            const float* __restrict__ freqs, const float* __restrict__ tempp,
                            float* __restrict__ dst, int Ntok, int gw, float sp)
{
    int idx = blockIdx.x * blockDim.x + threadIdx.x;
    if (idx >= Bb * Hh * Ntok) return;
    int n = idx % Ntok, bh = idx / Ntok;
    int h = bh % Hh, b = bh / Hh;
    const float* row = src + ((long long)(b * Ntok + n)) * srow + soff + h * HDc;
    float c0 = (float)(n / gw) * sp;
    float c1 = (float)(n % gw) * sp;
    float sc = tempp ? tempp[0] : 1.f;
    float* o = dst + (long long)idx * HDc;
    #pragma unroll
    for (int tt = 0; tt < 8; tt++) {
        float f = freqs[h * 8 + tt];
        float ang = ((tt < 4) ? c0 : c1) * f;
        float sn, cs;
        sincosf(ang, &sn, &cs);
        float x1 = row[2 * tt], x2 = row[2 * tt + 1];
        o[2 * tt]     = tfr(sc * (x1 * cs - x2 * sn));
        o[2 * tt + 1] = tfr(sc * (x1 * sn + x2 * cs));
    }
    #pragma unroll
    for (int d = 16; d < 32; d++) o[d] = tfr(sc * row[d]);
}

__global__ void build_vT_kernel(const float* __restrict__ kv, float* __restrict__ vT)
{
    long long idx = (long long)blockIdx.x * blockDim.x + threadIdx.x;
    if (idx >= (long long)BH * HDc * NK) return;
    int j = (int)(idx % NK);
    int r = (int)(idx / NK);
    int d = r % HDc, bh = r / HDc;
    int h = bh % Hh, b = bh / Hh;
    vT[idx] = kv[((long long)(b * NK + j)) * (2 * Dm) + Dm + h * HDc + d];
}

__global__ void vscale_kernel(const float* __restrict__ vT, const float* __restrict__ csum,
                              float* __restrict__ vs)
{
    long long idx = (long long)blockIdx.x * blockDim.x + threadIdx.x;
    if (idx >= (long long)BH * HDc * NK) return;
    int j = (int)(idx % NK);
    int bh = (int)(idx / ((long long)HDc * NK));
    vs[idx] = tfr(vT[idx] / (csum[bh * NK + j] + EPSF));
}

// fused softmax (row) + column-sum accumulation. 8 rows per block.
// ROUND: tf32-round the stored probabilities (internal iters only).
template<bool ROUND>
__global__ void softmax_csum_kernel(float* __restrict__ S, float* __restrict__ csum)
{
    const int bh = blockIdx.y;
    const int t = threadIdx.x, lane = t & 31, w = t >> 5;
    __shared__ float sm[8];
    float part[16];
    #pragma unroll
    for (int i = 0; i < 16; i++) part[i] = 0.f;
    S += (long long)bh * NQ * NK;

    for (int r = 0; r < 8; r++) {
        int row = blockIdx.x * 8 + r;
        if (row >= NQ) break;
        float* p = S + (long long)row * NK;
        float4 v[4];
        #pragma unroll
        for (int u = 0; u < 4; u++) v[u] = *(float4*)(p + t * 4 + u * 1024);
        float mx = -INFINITY;
        #pragma unroll
        for (int u = 0; u < 4; u++) {
            mx = fmaxf(mx, fmaxf(fmaxf(v[u].x, v[u].y), fmaxf(v[u].z, v[u].w)));
        }
        #pragma unroll
        for (int o = 16; o > 0; o >>= 1) mx = fmaxf(mx, __shfl_xor_sync(0xffffffffu, mx, o));
        if (lane == 0) sm[w] = mx;
        __syncthreads();
        mx = sm[0];
        #pragma unroll
        for (int i = 1; i < 8; i++) mx = fmaxf(mx, sm[i]);
        __syncthreads();
        float s = 0.f;
        #pragma unroll
        for (int u = 0; u < 4; u++) {
            v[u].x = __expf(v[u].x - mx); v[u].y = __expf(v[u].y - mx);
            v[u].z = __expf(v[u].z - mx); v[u].w = __expf(v[u].w - mx);
            s += v[u].x + v[u].y + v[u].z + v[u].w;
        }
        #pragma unroll
        for (int o = 16; o > 0; o >>= 1) s += __shfl_xor_sync(0xffffffffu, s, o);
        if (lane == 0) sm[w] = s;
        __syncthreads();
        s = sm[0] + sm[1] + sm[2] + sm[3] + sm[4] + sm[5] + sm[6] + sm[7];
        __syncthreads();
        float inv = 1.f / s;
        #pragma unroll
        for (int u = 0; u < 4; u++) {
            float q0 = v[u].x * inv, q1 = v[u].y * inv, q2 = v[u].z * inv, q3 = v[u].w * inv;
            if (ROUND) { q0 = tfr(q0); q1 = tfr(q1); q2 = tfr(q2); q3 = tfr(q3); }
            part[u * 4 + 0] += q0; part[u * 4 + 1] += q1;
            part[u * 4 + 2] += q2; part[u * 4 + 3] += q3;
            *(float4*)(p + t * 4 + u * 1024) = make_float4(q0, q1, q2, q3);
        }
    }
    #pragma unroll
    for (int u = 0; u < 4; u++)
        #pragma unroll
        for (int e = 0; e < 4; e++)
            atomicAdd(&csum[bh * NK + t * 4 + u * 1024 + e], part[u * 4 + e]);
}

__global__ void gelu_kernel(float* __restrict__ h, long long n)
{
    long long idx = (long long)blockIdx.x * blockDim.x + threadIdx.x;
    if (idx >= n) return;
    float v = h[idx];
    h[idx] = tfr(0.5f * v * (1.f + erff(v * 0.70710678118654752f)));
}

__global__ void out_x_kernel(float* __restrict__ out, const float* __restrict__ x)
{
    int idx = blockIdx.x * blockDim.x + threadIdx.x;
    if (idx >= MROWS * Dm) return;
    out[idx] = x[idx];
}

__global__ void out_q_kernel(float* __restrict__ outq, const float* __restrict__ outk,
                             const float* __restrict__ csum)
{
    long long idx = (long long)blockIdx.x * blockDim.x + threadIdx.x;
    if (idx >= (long long)BH * NQ * NK) return;
    int j = (int)(idx % NK);
    int bh = (int)(idx / ((long long)NQ * NK));
    outq[idx] = outk[idx] / (csum[bh * NK + j] + EPSF);
}

// ---------------- host ----------------
extern "C" void kernel_launch(void* const* d_in, const int* in_sizes, int n_in,
                              void* d_out, int out_size)
{
    const float* x      = (const float*)d_in[0];
    const float* conv_w = (const float*)d_in[1];
    const float* conv_b = (const float*)d_in[2];
    const float* kv_w   = (const float*)d_in[3];
    const float* kv_b   = (const float*)d_in[4];
    const float* q_w    = (const float*)d_in[5];
    const float* q_b    = (const float*)d_in[6];
    const float* w1     = (const float*)d_in[7];
    const float* b1m    = (const float*)d_in[8];
    const float* w2     = (const float*)d_in[9];
    const float* b2m    = (const float*)d_in[10];
    const float* g1     = (const float*)d_in[11];
    const float* b1g    = (const float*)d_in[12];
    const float* g2     = (const float*)d_in[13];
    const float* b2g    = (const float*)d_in[14];
    const float* g3     = (const float*)d_in[15];
    const float* b3g    = (const float*)d_in[16];
    const float* temp   = (const float*)d_in[17];
    const float* freqs  = (const float*)d_in[18];
    float* out = (float*)d_out;

    static float *p_convR=0,*p_convC=0,*p_xout=0,*p_kv=0,*p_k=0,*p_vT=0,*p_vs=0,*p_q=0,
                 *p_qlin=0,*p_attn=0,*p_csum=0,*p_upd=0,*p_h1=0,*p_h2=0,
                 *p_kvwT=0,*p_qwT=0,*p_w1T=0,*p_w2T=0;
    const int SM128 = (3*128*20 + 3*128*20) * 4;   // 61440
    const int SM64  = (3*128*20 + 3*64*20) * 4;    // 46080
    if (!p_convR) {
        void* t;
        cudaGetSymbolAddress(&t, g_convR); p_convR = (float*)t;
        cudaGetSymbolAddress(&t, g_convC); p_convC = (float*)t;
        cudaGetSymbolAddress(&t, g_xout);  p_xout  = (float*)t;
        cudaGetSymbolAddress(&t, g_kv);    p_kv    = (float*)t;
        cudaGetSymbolAddress(&t, g_k);     p_k     = (float*)t;
        cudaGetSymbolAddress(&t, g_vT);    p_vT    = (float*)t;
        cudaGetSymbolAddress(&t, g_vs);    p_vs    = (float*)t;
        cudaGetSymbolAddress(&t, g_q);     p_q     = (float*)t;
        cudaGetSymbolAddress(&t, g_qlin);  p_qlin  = (float*)t;
        cudaGetSymbolAddress(&t, g_attn);  p_attn  = (float*)t;
        cudaGetSymbolAddress(&t, g_csum);  p_csum  = (float*)t;
        cudaGetSymbolAddress(&t, g_upd);   p_upd   = (float*)t;
        cudaGetSymbolAddress(&t, g_h1);    p_h1    = (float*)t;
        cudaGetSymbolAddress(&t, g_h2);    p_h2    = (float*)t;
        cudaGetSymbolAddress(&t, g_kvwT);  p_kvwT  = (float*)t;
        cudaGetSymbolAddress(&t, g_qwT);   p_qwT   = (float*)t;
        cudaGetSymbolAddress(&t, g_w1T);   p_w1T   = (float*)t;
        cudaGetSymbolAddress(&t, g_w2T);   p_w2T   = (float*)t;
        cudaFuncSetAttribute(gemm_tc<128,true, true >, cudaFuncAttributeMaxDynamicSharedMemorySize, SM128);
        cudaFuncSetAttribute(gemm_tc<128,false,true >, cudaFuncAttributeMaxDynamicSharedMemorySize, SM128);
        cudaFuncSetAttribute(gemm_tc<128,false,false>, cudaFuncAttributeMaxDynamicSharedMemorySize, SM128);
        cudaFuncSetAttribute(gemm_tc<64, false,true >, cudaFuncAttributeMaxDynamicSharedMemorySize, SM64);
        cudaFuncSetAttribute(gemm_tc<64, false,false>, cudaFuncAttributeMaxDynamicSharedMemorySize, SM64);
    }

    float* outq = out + (long long)MROWS * Dm;
    float* outk = outq + (long long)BH * NQ * NK;

    const int TB = 256;
    reorder_convw<<<(int)(((long long)Dm*KCOL + TB-1)/TB), TB>>>(conv_w, p_convR);
    transpose_kn<<<(Dm*2*Dm + TB-1)/TB, TB>>>(kv_w, p_kvwT, Dm, 2*Dm);
    transpose_kn<<<(Dm*Dm   + TB-1)/TB, TB>>>(q_w,  p_qwT,  Dm, Dm);
    transpose_kn<<<(Dm*4*Dm + TB-1)/TB, TB>>>(w1,   p_w1T,  Dm, 4*Dm);
    transpose_kn<<<(4*Dm*Dm + TB-1)/TB, TB>>>(w2,   p_w2T,  4*Dm, Dm);

    // conv: implicit im2col, split-K 8
    fill_bias_kernel<<<(MROWS*Dm + TB-1)/TB, TB>>>(p_convC, conv_b, (long long)MROWS*Dm, Dm);
    gemm_tc<128,true,true><<<dim3(3, 8, 8), 256, SM128>>>(x, p_convR, p_convC, (const float*)0,
                                                          MROWS, Dm, KCOL, 8, 0, 0, 0);
    ln_kernel<<<MROWS, 128>>>(p_convC, g1, b1g, p_xout, 0, 0);

    // loop-invariant kv / k / vT
    gemm_tc<128,false,true><<<dim3(6, 64, 1), 256, SM128>>>(x, p_kvwT, p_kv, kv_b,
                                                            NTOK, 2*Dm, Dm, 1, 0, 0, 0);
    rose_kernel<<<(BH*NK + 127)/128, 128>>>(p_kv, 2*Dm, 0, freqs, temp, p_k, NK, GWc, 1.0f);
    build_vT_kernel<<<(int)(((long long)BH*HDc*NK + TB-1)/TB), TB>>>(p_kv, p_vT);

    for (int it = 0; it < ITERS; ++it) {
        const bool last = (it == ITERS - 1);
        float* S = last ? outk : p_attn;
        // q projection (split-K 8, bias prefilled)
        fill_bias_kernel<<<(MROWS*Dm + TB-1)/TB, TB>>>(p_qlin, q_b, (long long)MROWS*Dm, Dm);
        gemm_tc<128,false,true><<<dim3(3, 8, 8), 256, SM128>>>(p_xout, p_qwT, p_qlin, (const float*)0,
                                                               MROWS, Dm, Dm, 8, 0, 0, 0);
        rose_kernel<<<(BH*NQ + 127)/128, 128>>>(p_qlin, Dm, 0, freqs, (const float*)0, p_q, NQ, QG, 3.0f);
        // scores
        gemm_tc<128,false,false><<<dim3(32, 4, BH), 256, SM128>>>(p_q, p_k, S, (const float*)0,
                                                                  NQ, NK, HDc, 1,
                                                                  (long long)NQ*HDc, (long long)NK*HDc, (long long)NQ*NK);
        // fused softmax + colsum
        cudaMemsetAsync(p_csum, 0, (size_t)BH * NK * sizeof(float));
        if (last) softmax_csum_kernel<false><<<dim3(61, BH), 256>>>(S, p_csum);
        else      softmax_csum_kernel<true ><<<dim3(61, BH), 256>>>(S, p_csum);
        vscale_kernel<<<(int)(((long long)BH*HDc*NK + TB-1)/TB), TB>>>(p_vT, p_csum, p_vs);
        if (last)
            out_q_kernel<<<(int)(((long long)BH*NQ*NK + TB-1)/TB), TB>>>(outq, outk, p_csum);
        // upd = attn_k @ vs^T (split-K 4)
        cudaMemsetAsync(p_upd, 0, (size_t)BH * NQ * HDc * sizeof(float));
        if (last)
            gemm_tc<64,false,true><<<dim3(1, 4, BH * 4), 256, SM64>>>(S, p_vs, p_upd, (const float*)0,
                                                                      NQ, HDc, NK, 4,
                                                                      (long long)NQ*NK, (long long)HDc*NK, (long long)NQ*HDc);
        else
            gemm_tc<64,false,false><<<dim3(1, 4, BH * 4), 256, SM64>>>(S, p_vs, p_upd, (const float*)0,
                                                                       NQ, HDc, NK, 4,
                                                                       (long long)NQ*NK, (long long)HDc*NK, (long long)NQ*HDc);
        ln_kernel<<<MROWS, 128>>>(p_upd, g2, b2g, p_xout, 1, 1);
        // MLP (split-K + separate gelu that rounds h1)
        fill_bias_kernel<<<(MROWS*4*Dm + TB-1)/TB, TB>>>(p_h1, b1m, (long long)MROWS*4*Dm, 4*Dm);
        gemm_tc<128,false,true><<<dim3(12, 8, 2), 256, SM128>>>(p_xout, p_w1T, p_h1, (const float*)0,
                                                                MROWS, 4*Dm, Dm, 2, 0, 0, 0);
        gelu_kernel<<<(int)(((long long)MROWS*4*Dm + TB-1)/TB), TB>>>(p_h1, (long long)MROWS*4*Dm);
        fill_bias_kernel<<<(MROWS*Dm + TB-1)/TB, TB>>>(p_h2, b2m, (long long)MROWS*Dm, Dm);
        gemm_tc<128,false,false><<<dim3(3, 8, 8), 256, SM128>>>(p_h1, p_w2T, p_h2, (const float*)0,
                                                                MROWS, Dm, 4*Dm, 8, 0, 0, 0);
        ln_kernel<<<MROWS, 128>>>(p_h2, g3, b3g, p_xout, 0, 1);
    }

    out_x_kernel<<<(MROWS*Dm + TB-1)/TB, TB>>>(out, p_xout);
    (void)in_sizes; (void)n_in; (void)out_size;
}